// round 15
// baseline (speedup 1.0000x reference)
#include <cuda_runtime.h>
#include <cstdint>

#define BATCH 4
#define SEQ   4096
#define EMBED 768
#define HEAD  64
#define NQB   (SEQ / 64)

// Scratch for projected Q, K, V  (3 x 4 MB). __device__ globals: no allocation.
__device__ float g_Q[BATCH * SEQ * HEAD];
__device__ float g_K[BATCH * SEQ * HEAD];
__device__ float g_V[BATCH * SEQ * HEAD];

// XOR-granule swizzle for [a][b] tiles with 64-float rows.
__device__ __forceinline__ int swz4(int a, int b4) {
    return a * 64 + ((((b4 >> 2) ^ (a >> 2)) & 15) << 2);
}
__device__ __forceinline__ int swz1(int a, int b) {
    return swz4(a, b & ~3) + (b & 3);
}

__device__ __forceinline__ float ex2f(float x) {
    float r; asm("ex2.approx.ftz.f32 %0, %1;" : "=f"(r) : "f"(x)); return r;
}

// ---------------------------------------------------------------------------
// QKV projection (R6 scalar version — measured ~111 us, at the fp32 wall)
// ---------------------------------------------------------------------------
__global__ __launch_bounds__(256) void qkv_proj(
    const float* __restrict__ x,
    const float* __restrict__ Wq, const float* __restrict__ bq,
    const float* __restrict__ Wk, const float* __restrict__ bk,
    const float* __restrict__ Wv, const float* __restrict__ bv)
{
    __shared__ float As[32 * 64];   // x tile, transposed: As[k][m] (swizzled)
    __shared__ float Bs[32 * 64];   // W tile: Bs[k][h]

    const float* W; const float* bias; float* out;
    if (blockIdx.y == 0)      { W = Wq; bias = bq; out = g_Q; }
    else if (blockIdx.y == 1) { W = Wk; bias = bk; out = g_K; }
    else                      { W = Wv; bias = bv; out = g_V; }

    const int tid = threadIdx.x;
    const int ty = tid >> 4;
    const int tx = tid & 15;
    const int mBase = blockIdx.x * 64;

    float c[4][4] = {};

    for (int k0 = 0; k0 < EMBED; k0 += 32) {
        #pragma unroll
        for (int i = 0; i < 2; i++) {
            int f4 = tid + i * 256;
            int m  = f4 >> 3;
            int kq = (f4 & 7) << 2;
            float4 v = *(const float4*)&x[(size_t)(mBase + m) * EMBED + k0 + kq];
            As[swz1(kq + 0, m)] = v.x;
            As[swz1(kq + 1, m)] = v.y;
            As[swz1(kq + 2, m)] = v.z;
            As[swz1(kq + 3, m)] = v.w;
            int kk = f4 >> 4;
            int h  = (f4 & 15) << 2;
            *(float4*)&Bs[kk * 64 + h] = *(const float4*)&W[(size_t)(k0 + kk) * HEAD + h];
        }
        __syncthreads();

        #pragma unroll
        for (int kk = 0; kk < 32; kk++) {
            float4 a4 = *(const float4*)&As[swz4(kk, ty << 2)];
            float4 b4 = *(const float4*)&Bs[kk * 64 + (tx << 2)];
            float a[4] = {a4.x, a4.y, a4.z, a4.w};
            float b[4] = {b4.x, b4.y, b4.z, b4.w};
            #pragma unroll
            for (int r = 0; r < 4; r++)
                #pragma unroll
                for (int cc = 0; cc < 4; cc++)
                    c[r][cc] = fmaf(a[r], b[cc], c[r][cc]);
        }
        __syncthreads();
    }

    float4 bb = *(const float4*)&bias[tx << 2];
    float bv4[4] = {bb.x, bb.y, bb.z, bb.w};
    #pragma unroll
    for (int r = 0; r < 4; r++) {
        float4 o = make_float4(c[r][0] + bv4[0], c[r][1] + bv4[1],
                               c[r][2] + bv4[2], c[r][3] + bv4[3]);
        *(float4*)&out[(size_t)(mBase + (ty << 2) + r) * HEAD + (tx << 2)] = o;
    }
}

// ---------------------------------------------------------------------------
// Flash attention, causal. 64x64 flash tiles, HEAD = 64.
// 128 threads (8 x 16), 8x4 register micro-tile:
//   per kk: 3 LDS.128 (2 broadcast) -> 32 FFMA : crossbar ~0.4x of fma floor
//   (vs 1.0x with the old 4x4 tile — L1 was co-binding at 48%).
// 48 KB static smem, __launch_bounds__(128,4): 4 blocks/SM, 16 warps,
// all 256 blocks in one wave.
// K tile LDG-hoisted before the barrier; V tile via cp.async (waited just
// before the PV barrier — latency hidden under QK+softmax).
// smem: Qs[h][r] (swizzled), KPs (K^T; reused as P^T), Vs.
// ---------------------------------------------------------------------------
__global__ __launch_bounds__(128, 4) void attn(float* __restrict__ out)
{
    __shared__ float Qs [64 * 64];
    __shared__ float KPs[64 * 64];
    __shared__ float Vs [64 * 64];

    const int b   = blockIdx.y;
    const int qb  = NQB - 1 - blockIdx.x;   // heavy blocks first
    const int tid = threadIdx.x;
    const int ty  = tid >> 4;               // 0..7 : 8 query rows each
    const int tx  = tid & 15;               // 0..15: 4 key/head cols each
    const int lr  = tid >> 4;               // load row base (0..7)
    const int lh  = (tid & 15) << 2;        // load col base

    const float* Qg = g_Q + ((size_t)b * SEQ + (size_t)qb * 64) * HEAD;
    const float* Kg = g_K + (size_t)b * SEQ * HEAD;
    const float* Vg = g_V + (size_t)b * SEQ * HEAD;

    // Load Q tile transposed: Qs[h][r]   (8 float4 per thread)
    #pragma unroll
    for (int i = 0; i < 8; i++) {
        int f4 = tid + i * 128;          // 0..1023
        int r  = f4 >> 4;                // query row in tile
        int h4 = (f4 & 15) << 2;
        float4 v = *(const float4*)&Qg[(size_t)r * HEAD + h4];
        Qs[swz1(h4 + 0, r)] = v.x;
        Qs[swz1(h4 + 1, r)] = v.y;
        Qs[swz1(h4 + 2, r)] = v.z;
        Qs[swz1(h4 + 3, r)] = v.w;
    }

    float m_r[8], l_r[8], acc[8][4];
    #pragma unroll
    for (int r = 0; r < 8; r++) {
        m_r[r] = -1e30f; l_r[r] = 0.0f;
        #pragma unroll
        for (int cc = 0; cc < 4; cc++) acc[r][cc] = 0.0f;
    }

    // scale folded with log2(e): softmax in exp2 domain
    const float SCALE2 = 0.125f * 1.44269504088896340736f;

    for (int kb = 0; kb <= qb; kb++) {
        const float* Kt = Kg + (size_t)kb * 64 * HEAD;
        const float* Vt = Vg + (size_t)kb * 64 * HEAD;

        // hoisted K LDGs: overlap the barrier wait
        float4 kreg[8];
        #pragma unroll
        for (int i = 0; i < 8; i++)
            kreg[i] = *(const float4*)&Kt[(size_t)(lr + 8 * i) * HEAD + lh];

        __syncthreads();   // S1: prev PV finished reading KPs/Vs

        // V tile via cp.async (no register staging; completes during QK)
        #pragma unroll
        for (int i = 0; i < 8; i++) {
            int r = lr + 8 * i;
            uint32_t dst = (uint32_t)__cvta_generic_to_shared(&Vs[swz4(r, lh)]);
            asm volatile("cp.async.cg.shared.global [%0], [%1], 16;"
                         :: "r"(dst), "l"(&Vt[(size_t)r * HEAD + lh]));
        }
        asm volatile("cp.async.commit_group;");

        // store K transposed (swizzled)
        #pragma unroll
        for (int i = 0; i < 8; i++) {
            int r = lr + 8 * i;
            float kv[4] = {kreg[i].x, kreg[i].y, kreg[i].z, kreg[i].w};
            #pragma unroll
            for (int c = 0; c < 4; c++)
                KPs[swz1(lh + c, r)] = kv[c];
        }
        __syncthreads();   // S2: Ks ready (iter 0: Qs ready too)

        // ---- S = Q K^T (8x4), full unroll: immediate LDS addresses --------
        float s[8][4] = {};
        #pragma unroll
        for (int kk = 0; kk < HEAD; kk++) {
            float4 qA = *(const float4*)&Qs [swz4(kk, ty << 3)];       // rows 8ty..+3
            float4 qB = *(const float4*)&Qs [swz4(kk, (ty << 3) + 4)]; // rows +4..+7
            float4 k4 = *(const float4*)&KPs[swz4(kk, tx << 2)];
            float qa[8] = {qA.x, qA.y, qA.z, qA.w, qB.x, qB.y, qB.z, qB.w};
            float ka[4] = {k4.x, k4.y, k4.z, k4.w};
            #pragma unroll
            for (int r = 0; r < 8; r++)
                #pragma unroll
                for (int cc = 0; cc < 4; cc++)
                    s[r][cc] = fmaf(qa[r], ka[cc], s[r][cc]);
        }

        // scale + causal mask (diagonal tile only)
        if (kb == qb) {
            #pragma unroll
            for (int r = 0; r < 8; r++)
                #pragma unroll
                for (int cc = 0; cc < 4; cc++) {
                    int trow = (ty << 3) + r, tcol = (tx << 2) + cc;
                    s[r][cc] = (tcol <= trow) ? s[r][cc] * SCALE2 : -1e30f;
                }
        } else {
            #pragma unroll
            for (int r = 0; r < 8; r++)
                #pragma unroll
                for (int cc = 0; cc < 4; cc++) s[r][cc] *= SCALE2;
        }

        // online softmax per row (row lives in a 16-lane half-warp group)
        #pragma unroll
        for (int r = 0; r < 8; r++) {
            float m0 = fmaxf(fmaxf(s[r][0], s[r][1]), fmaxf(s[r][2], s[r][3]));
            #pragma unroll
            for (int off = 8; off > 0; off >>= 1)
                m0 = fmaxf(m0, __shfl_xor_sync(0xffffffffu, m0, off));
            float newm  = fmaxf(m_r[r], m0);
            float alpha = ex2f(m_r[r] - newm);
            float lsum  = 0.0f;
            #pragma unroll
            for (int cc = 0; cc < 4; cc++) {
                float e = ex2f(s[r][cc] - newm);
                s[r][cc] = e;                 // s becomes P
                lsum += e;
            }
            #pragma unroll
            for (int off = 8; off > 0; off >>= 1)
                lsum += __shfl_xor_sync(0xffffffffu, lsum, off);
            l_r[r] = l_r[r] * alpha + lsum;
            m_r[r] = newm;
            #pragma unroll
            for (int cc = 0; cc < 4; cc++) acc[r][cc] *= alpha;
        }

        __syncthreads();   // S3: all K reads done; KPs becomes P^T
        #pragma unroll
        for (int cc = 0; cc < 4; cc++) {
            int j = (tx << 2) + cc;
            *(float4*)&KPs[swz4(j, ty << 3)] =
                make_float4(s[0][cc], s[1][cc], s[2][cc], s[3][cc]);
            *(float4*)&KPs[swz4(j, (ty << 3) + 4)] =
                make_float4(s[4][cc], s[5][cc], s[6][cc], s[7][cc]);
        }
        asm volatile("cp.async.wait_group 0;");   // Vs writes landed
        __syncthreads();   // S4: P^T + Vs ready

        // ---- O += P V (8x4), full unroll ----------------------------------
        #pragma unroll
        for (int j = 0; j < 64; j++) {
            float4 pA = *(const float4*)&KPs[swz4(j, ty << 3)];
            float4 pB = *(const float4*)&KPs[swz4(j, (ty << 3) + 4)];
            float4 v4 = *(const float4*)&Vs [swz4(j, tx << 2)];
            float pa[8] = {pA.x, pA.y, pA.z, pA.w, pB.x, pB.y, pB.z, pB.w};
            float va[4] = {v4.x, v4.y, v4.z, v4.w};
            #pragma unroll
            for (int r = 0; r < 8; r++)
                #pragma unroll
                for (int cc = 0; cc < 4; cc++)
                    acc[r][cc] = fmaf(pa[r], va[cc], acc[r][cc]);
        }
    }

    // epilogue: normalize and store
    float* Og = out + ((size_t)b * SEQ + (size_t)qb * 64) * HEAD;
    #pragma unroll
    for (int r = 0; r < 8; r++) {
        float inv = 1.0f / l_r[r];
        float4 o = make_float4(acc[r][0] * inv, acc[r][1] * inv,
                               acc[r][2] * inv, acc[r][3] * inv);
        *(float4*)&Og[(size_t)((ty << 3) + r) * HEAD + (tx << 2)] = o;
    }
}

// ---------------------------------------------------------------------------
extern "C" void kernel_launch(void* const* d_in, const int* in_sizes, int n_in,
                              void* d_out, int out_size)
{
    const float* x  = (const float*)d_in[0];
    const float* Wq = (const float*)d_in[1];
    const float* bq = (const float*)d_in[2];
    const float* Wk = (const float*)d_in[3];
    const float* bk = (const float*)d_in[4];
    const float* Wv = (const float*)d_in[5];
    const float* bv = (const float*)d_in[6];
    float* out = (float*)d_out;

    // same carveout preference on BOTH kernels: avoids per-replay SM
    // shared/L1 reconfiguration between proj and attn
    cudaFuncSetAttribute(qkv_proj, cudaFuncAttributePreferredSharedMemoryCarveout,
                         (int)cudaSharedmemCarveoutMaxShared);
    cudaFuncSetAttribute(attn, cudaFuncAttributePreferredSharedMemoryCarveout,
                         (int)cudaSharedmemCarveoutMaxShared);

    dim3 gp((BATCH * SEQ) / 64, 3);
    qkv_proj<<<gp, 256>>>(x, Wq, bq, Wk, bk, Wv, bv);

    dim3 ga(NQB, BATCH);
    attn<<<ga, 128>>>(out);
}

// round 16
// speedup vs baseline: 1.5651x; 1.5651x over previous
#include <cuda_runtime.h>
#include <cstdint>

#define BATCH 4
#define SEQ   4096
#define EMBED 768
#define HEAD  64
#define NQB   (SEQ / 64)
#define NROW  (BATCH * SEQ)

// Scratch (device globals: no allocation).
__device__ float g_Q[NROW * HEAD];
__device__ float g_K[NROW * HEAD];
__device__ float g_V[NROW * HEAD];
// split-KV partials: unnormalized acc + running (m, l) per row, per split
__device__ float g_pAcc[2][NROW * HEAD];
__device__ float g_pM  [2][NROW];
__device__ float g_pL  [2][NROW];

// XOR-granule swizzle for [a][b] tiles with 64-float rows.
__device__ __forceinline__ int swz4(int a, int b4) {
    return a * 64 + ((((b4 >> 2) ^ (a >> 2)) & 15) << 2);
}
__device__ __forceinline__ int swz1(int a, int b) {
    return swz4(a, b & ~3) + (b & 3);
}

__device__ __forceinline__ float ex2f(float x) {
    float r; asm("ex2.approx.ftz.f32 %0, %1;" : "=f"(r) : "f"(x)); return r;
}

// ---------------------------------------------------------------------------
// QKV projection (exact R6 version — measured ~111 us; no attr fiddling)
// ---------------------------------------------------------------------------
__global__ __launch_bounds__(256) void qkv_proj(
    const float* __restrict__ x,
    const float* __restrict__ Wq, const float* __restrict__ bq,
    const float* __restrict__ Wk, const float* __restrict__ bk,
    const float* __restrict__ Wv, const float* __restrict__ bv)
{
    __shared__ float As[32 * 64];   // x tile, transposed: As[k][m] (swizzled)
    __shared__ float Bs[32 * 64];   // W tile: Bs[k][h]

    const float* W; const float* bias; float* out;
    if (blockIdx.y == 0)      { W = Wq; bias = bq; out = g_Q; }
    else if (blockIdx.y == 1) { W = Wk; bias = bk; out = g_K; }
    else                      { W = Wv; bias = bv; out = g_V; }

    const int tid = threadIdx.x;
    const int ty = tid >> 4;
    const int tx = tid & 15;
    const int mBase = blockIdx.x * 64;

    float c[4][4] = {};

    for (int k0 = 0; k0 < EMBED; k0 += 32) {
        #pragma unroll
        for (int i = 0; i < 2; i++) {
            int f4 = tid + i * 256;
            int m  = f4 >> 3;
            int kq = (f4 & 7) << 2;
            float4 v = *(const float4*)&x[(size_t)(mBase + m) * EMBED + k0 + kq];
            As[swz1(kq + 0, m)] = v.x;
            As[swz1(kq + 1, m)] = v.y;
            As[swz1(kq + 2, m)] = v.z;
            As[swz1(kq + 3, m)] = v.w;
            int kk = f4 >> 4;
            int h  = (f4 & 15) << 2;
            *(float4*)&Bs[kk * 64 + h] = *(const float4*)&W[(size_t)(k0 + kk) * HEAD + h];
        }
        __syncthreads();

        #pragma unroll
        for (int kk = 0; kk < 32; kk++) {
            float4 a4 = *(const float4*)&As[swz4(kk, ty << 2)];
            float4 b4 = *(const float4*)&Bs[kk * 64 + (tx << 2)];
            float a[4] = {a4.x, a4.y, a4.z, a4.w};
            float b[4] = {b4.x, b4.y, b4.z, b4.w};
            #pragma unroll
            for (int r = 0; r < 4; r++)
                #pragma unroll
                for (int cc = 0; cc < 4; cc++)
                    c[r][cc] = fmaf(a[r], b[cc], c[r][cc]);
        }
        __syncthreads();
    }

    float4 bb = *(const float4*)&bias[tx << 2];
    float bv4[4] = {bb.x, bb.y, bb.z, bb.w};
    #pragma unroll
    for (int r = 0; r < 4; r++) {
        float4 o = make_float4(c[r][0] + bv4[0], c[r][1] + bv4[1],
                               c[r][2] + bv4[2], c[r][3] + bv4[3]);
        *(float4*)&out[(size_t)(mBase + (ty << 2) + r) * HEAD + (tx << 2)] = o;
    }
}

// ---------------------------------------------------------------------------
// Flash attention, causal, SPLIT-KV x2.
// Block = 128 threads (8 x 16), 8x4 register micro-tile over a 64x64 tile.
// Split s (blockIdx.z) processes key blocks kb = s, s+2, ... <= qb with its
// own online softmax; writes UNNORMALIZED acc + (m, l) partials.
// Grid 512 blocks -> ~3.5 blocks/SM (48 KB smem x4 = 192 KB, 128 regs x4 =
// full RF) -> ~14 warps/SM: restores the latency cover R15 lost.
// K tile LDG-hoisted above barrier; V tile via cp.async.
// ---------------------------------------------------------------------------
__global__ __launch_bounds__(128, 4) void attn_split()
{
    __shared__ float Qs [64 * 64];
    __shared__ float KPs[64 * 64];
    __shared__ float Vs [64 * 64];

    const int b   = blockIdx.y;
    const int qb  = NQB - 1 - blockIdx.x;   // heavy blocks first
    const int sp  = blockIdx.z;             // split: key blocks kb % 2 == sp
    const int tid = threadIdx.x;
    const int ty  = tid >> 4;               // 0..7 : 8 query rows each
    const int tx  = tid & 15;               // 0..15: 4 key/head cols each
    const int lr  = tid >> 4;               // load row base (0..7)
    const int lh  = (tid & 15) << 2;        // load col base

    const float* Qg = g_Q + ((size_t)b * SEQ + (size_t)qb * 64) * HEAD;
    const float* Kg = g_K + (size_t)b * SEQ * HEAD;
    const float* Vg = g_V + (size_t)b * SEQ * HEAD;

    // Load Q tile transposed: Qs[h][r]   (8 float4 per thread)
    #pragma unroll
    for (int i = 0; i < 8; i++) {
        int f4 = tid + i * 128;          // 0..1023
        int r  = f4 >> 4;
        int h4 = (f4 & 15) << 2;
        float4 v = *(const float4*)&Qg[(size_t)r * HEAD + h4];
        Qs[swz1(h4 + 0, r)] = v.x;
        Qs[swz1(h4 + 1, r)] = v.y;
        Qs[swz1(h4 + 2, r)] = v.z;
        Qs[swz1(h4 + 3, r)] = v.w;
    }

    float m_r[8], l_r[8], acc[8][4];
    #pragma unroll
    for (int r = 0; r < 8; r++) {
        m_r[r] = -1e30f; l_r[r] = 0.0f;
        #pragma unroll
        for (int cc = 0; cc < 4; cc++) acc[r][cc] = 0.0f;
    }

    // scale folded with log2(e): softmax in exp2 domain
    const float SCALE2 = 0.125f * 1.44269504088896340736f;

    for (int kb = sp; kb <= qb; kb += 2) {
        const float* Kt = Kg + (size_t)kb * 64 * HEAD;
        const float* Vt = Vg + (size_t)kb * 64 * HEAD;

        // hoisted K LDGs: overlap the barrier wait
        float4 kreg[8];
        #pragma unroll
        for (int i = 0; i < 8; i++)
            kreg[i] = *(const float4*)&Kt[(size_t)(lr + 8 * i) * HEAD + lh];

        __syncthreads();   // prev PV finished reading KPs/Vs

        // V tile via cp.async (completes during QK+softmax)
        #pragma unroll
        for (int i = 0; i < 8; i++) {
            int r = lr + 8 * i;
            uint32_t dst = (uint32_t)__cvta_generic_to_shared(&Vs[swz4(r, lh)]);
            asm volatile("cp.async.cg.shared.global [%0], [%1], 16;"
                         :: "r"(dst), "l"(&Vt[(size_t)r * HEAD + lh]));
        }
        asm volatile("cp.async.commit_group;");

        // store K transposed (swizzled)
        #pragma unroll
        for (int i = 0; i < 8; i++) {
            int r = lr + 8 * i;
            float kv[4] = {kreg[i].x, kreg[i].y, kreg[i].z, kreg[i].w};
            #pragma unroll
            for (int c = 0; c < 4; c++)
                KPs[swz1(lh + c, r)] = kv[c];
        }
        __syncthreads();   // Ks ready (iter 0: Qs ready too)

        // ---- S = Q K^T (8x4), full unroll: immediate LDS addresses --------
        float s[8][4] = {};
        #pragma unroll
        for (int kk = 0; kk < HEAD; kk++) {
            float4 qA = *(const float4*)&Qs [swz4(kk, ty << 3)];
            float4 qB = *(const float4*)&Qs [swz4(kk, (ty << 3) + 4)];
            float4 k4 = *(const float4*)&KPs[swz4(kk, tx << 2)];
            float qa[8] = {qA.x, qA.y, qA.z, qA.w, qB.x, qB.y, qB.z, qB.w};
            float ka[4] = {k4.x, k4.y, k4.z, k4.w};
            #pragma unroll
            for (int r = 0; r < 8; r++)
                #pragma unroll
                for (int cc = 0; cc < 4; cc++)
                    s[r][cc] = fmaf(qa[r], ka[cc], s[r][cc]);
        }

        // scale + causal mask (diagonal tile only)
        if (kb == qb) {
            #pragma unroll
            for (int r = 0; r < 8; r++)
                #pragma unroll
                for (int cc = 0; cc < 4; cc++) {
                    int trow = (ty << 3) + r, tcol = (tx << 2) + cc;
                    s[r][cc] = (tcol <= trow) ? s[r][cc] * SCALE2 : -1e30f;
                }
        } else {
            #pragma unroll
            for (int r = 0; r < 8; r++)
                #pragma unroll
                for (int cc = 0; cc < 4; cc++) s[r][cc] *= SCALE2;
        }

        // online softmax per row (row lives in a 16-lane half-warp group)
        #pragma unroll
        for (int r = 0; r < 8; r++) {
            float m0 = fmaxf(fmaxf(s[r][0], s[r][1]), fmaxf(s[r][2], s[r][3]));
            #pragma unroll
            for (int off = 8; off > 0; off >>= 1)
                m0 = fmaxf(m0, __shfl_xor_sync(0xffffffffu, m0, off));
            float newm  = fmaxf(m_r[r], m0);
            float alpha = ex2f(m_r[r] - newm);
            float lsum  = 0.0f;
            #pragma unroll
            for (int cc = 0; cc < 4; cc++) {
                float e = ex2f(s[r][cc] - newm);
                s[r][cc] = e;                 // s becomes P
                lsum += e;
            }
            #pragma unroll
            for (int off = 8; off > 0; off >>= 1)
                lsum += __shfl_xor_sync(0xffffffffu, lsum, off);
            l_r[r] = l_r[r] * alpha + lsum;
            m_r[r] = newm;
            #pragma unroll
            for (int cc = 0; cc < 4; cc++) acc[r][cc] *= alpha;
        }

        __syncthreads();   // all K reads done; KPs becomes P^T
        #pragma unroll
        for (int cc = 0; cc < 4; cc++) {
            int j = (tx << 2) + cc;
            *(float4*)&KPs[swz4(j, ty << 3)] =
                make_float4(s[0][cc], s[1][cc], s[2][cc], s[3][cc]);
            *(float4*)&KPs[swz4(j, (ty << 3) + 4)] =
                make_float4(s[4][cc], s[5][cc], s[6][cc], s[7][cc]);
        }
        asm volatile("cp.async.wait_group 0;");   // Vs writes landed
        __syncthreads();   // P^T + Vs ready

        // ---- O += P V (8x4), full unroll ----------------------------------
        #pragma unroll
        for (int j = 0; j < 64; j++) {
            float4 pA = *(const float4*)&KPs[swz4(j, ty << 3)];
            float4 pB = *(const float4*)&KPs[swz4(j, (ty << 3) + 4)];
            float4 v4 = *(const float4*)&Vs [swz4(j, tx << 2)];
            float pa[8] = {pA.x, pA.y, pA.z, pA.w, pB.x, pB.y, pB.z, pB.w};
            float va[4] = {v4.x, v4.y, v4.z, v4.w};
            #pragma unroll
            for (int r = 0; r < 8; r++)
                #pragma unroll
                for (int cc = 0; cc < 4; cc++)
                    acc[r][cc] = fmaf(pa[r], va[cc], acc[r][cc]);
        }
    }

    // ---- epilogue: write UNNORMALIZED partials for this split -------------
    size_t rowBase = (size_t)b * SEQ + (size_t)qb * 64;
    float* accOut = g_pAcc[sp] + rowBase * HEAD;
    float* mOut   = g_pM[sp]   + rowBase;
    float* lOut   = g_pL[sp]   + rowBase;
    #pragma unroll
    for (int r = 0; r < 8; r++) {
        int row = (ty << 3) + r;
        if (tx == 0) { mOut[row] = m_r[r]; lOut[row] = l_r[r]; }
        *(float4*)&accOut[(size_t)row * HEAD + (tx << 2)] =
            make_float4(acc[r][0], acc[r][1], acc[r][2], acc[r][3]);
    }
}

// ---------------------------------------------------------------------------
// Combine the two splits:  O = (acc0*a0 + acc1*a1) / (l0*a0 + l1*a1),
// a_i = 2^(m_i - max(m0,m1)).  One float4 per thread; ~12 MB traffic.
// ---------------------------------------------------------------------------
__global__ __launch_bounds__(256) void combine(float* __restrict__ out)
{
    int idx = blockIdx.x * 256 + threadIdx.x;   // f4 index: NROW*16 total
    int row = idx >> 4;
    int c4  = (idx & 15) << 2;

    float m0 = g_pM[0][row], m1 = g_pM[1][row];
    float l0 = g_pL[0][row], l1 = g_pL[1][row];
    float m  = fmaxf(m0, m1);
    float a0 = ex2f(m0 - m), a1 = ex2f(m1 - m);
    float inv = 1.0f / (l0 * a0 + l1 * a1);

    float4 x0 = *(const float4*)&g_pAcc[0][(size_t)row * HEAD + c4];
    float4 x1 = *(const float4*)&g_pAcc[1][(size_t)row * HEAD + c4];
    float4 o  = make_float4((x0.x * a0 + x1.x * a1) * inv,
                            (x0.y * a0 + x1.y * a1) * inv,
                            (x0.z * a0 + x1.z * a1) * inv,
                            (x0.w * a0 + x1.w * a1) * inv);
    *(float4*)&out[(size_t)row * HEAD + c4] = o;
}

// ---------------------------------------------------------------------------
extern "C" void kernel_launch(void* const* d_in, const int* in_sizes, int n_in,
                              void* d_out, int out_size)
{
    const float* x  = (const float*)d_in[0];
    const float* Wq = (const float*)d_in[1];
    const float* bq = (const float*)d_in[2];
    const float* Wk = (const float*)d_in[3];
    const float* bk = (const float*)d_in[4];
    const float* Wv = (const float*)d_in[5];
    const float* bv = (const float*)d_in[6];
    float* out = (float*)d_out;

    dim3 gp((BATCH * SEQ) / 64, 3);
    qkv_proj<<<gp, 256>>>(x, Wq, bq, Wk, bk, Wv, bv);

    dim3 ga(NQB, BATCH, 2);
    attn_split<<<ga, 128>>>();

    combine<<<(NROW * 16) / 256, 256>>>(out);
}